// round 12
// baseline (speedup 1.0000x reference)
#include <cuda_runtime.h>
#include <cuda_bf16.h>

// SpanIndexEncoder: out[t] = sum over nodes n (n<num_nodes, s_n<=t<=e_n) of emb[n]
// SINGLE-KERNEL version. Decompose by feature column: block j owns one float4
// column (64 blocks x 1024 threads). Inside a block:
//   1. zero 8192 token bins in shared (128 KB)
//   2. scatter: per node, atomicAdd signed emb column into bins[s] / bins[e+1]
//   3. block-wide inclusive scan over the 8192 bins -> write out directly
// No global intermediates, no multi-node graph, no self-reset needed.

#define MAX_TOKENS 8192
#define FEAT       256
#define F4         (FEAT / 4)     // 64 float4 columns
#define NTHR       1024
#define PER_THR    (MAX_TOKENS / NTHR)   // 8 bins per thread

__global__ void __launch_bounds__(NTHR) span_onepass_kernel(
    const float* __restrict__ emb,
    const int*   __restrict__ starts,
    const int*   __restrict__ ends,
    const int*   __restrict__ num_nodes_p,
    float*       __restrict__ out)
{
    extern __shared__ float4 bins[];          // MAX_TOKENS entries = 128 KB
    __shared__ float4 wsum[32];

    const int j    = blockIdx.x;              // float4 column
    const int tid  = threadIdx.x;
    const int lane = tid & 31;
    const int wid  = tid >> 5;

    // ---- 1. zero bins ----
#pragma unroll
    for (int i = 0; i < PER_THR; ++i)
        bins[tid + i * NTHR] = make_float4(0.f, 0.f, 0.f, 0.f);
    __syncthreads();

    // ---- 2. scatter signed emb columns into token bins ----
    {
        const int nn = num_nodes_p[0];
        const float4* emb4 = reinterpret_cast<const float4*>(emb);
        for (int n = tid; n < nn; n += NTHR) {
            const int s = starts[n];
            const int e = ends[n];
            if (s <= e) {
                const float4 v = emb4[(size_t)n * F4 + j];
                float* b = reinterpret_cast<float*>(&bins[s]);
                atomicAdd(b + 0, v.x);
                atomicAdd(b + 1, v.y);
                atomicAdd(b + 2, v.z);
                atomicAdd(b + 3, v.w);
                const int e1 = e + 1;
                if (e1 < MAX_TOKENS) {
                    float* b2 = reinterpret_cast<float*>(&bins[e1]);
                    atomicAdd(b2 + 0, -v.x);
                    atomicAdd(b2 + 1, -v.y);
                    atomicAdd(b2 + 2, -v.z);
                    atomicAdd(b2 + 3, -v.w);
                }
            }
        }
    }
    __syncthreads();

    // ---- 3. block-wide inclusive scan over bins; write out ----
    // Thread owns bins [8*tid, 8*tid+8)
    float4 v[PER_THR];
#pragma unroll
    for (int i = 0; i < PER_THR; ++i) v[i] = bins[tid * PER_THR + i];
#pragma unroll
    for (int i = 1; i < PER_THR; ++i) {
        v[i].x += v[i-1].x; v[i].y += v[i-1].y; v[i].z += v[i-1].z; v[i].w += v[i-1].w;
    }

    const float4 tot = v[PER_THR - 1];
    float4 incl = tot;
#pragma unroll
    for (int d = 1; d < 32; d <<= 1) {
        const float tx = __shfl_up_sync(0xffffffffu, incl.x, d);
        const float ty = __shfl_up_sync(0xffffffffu, incl.y, d);
        const float tz = __shfl_up_sync(0xffffffffu, incl.z, d);
        const float tw = __shfl_up_sync(0xffffffffu, incl.w, d);
        if (lane >= d) { incl.x += tx; incl.y += ty; incl.z += tz; incl.w += tw; }
    }
    if (lane == 31) wsum[wid] = incl;
    __syncthreads();
    if (wid == 0) {
        float4 a = wsum[lane];
        float4 wi = a;
#pragma unroll
        for (int d = 1; d < 32; d <<= 1) {
            const float tx = __shfl_up_sync(0xffffffffu, wi.x, d);
            const float ty = __shfl_up_sync(0xffffffffu, wi.y, d);
            const float tz = __shfl_up_sync(0xffffffffu, wi.z, d);
            const float tw = __shfl_up_sync(0xffffffffu, wi.w, d);
            if (lane >= d) { wi.x += tx; wi.y += ty; wi.z += tz; wi.w += tw; }
        }
        wsum[lane] = make_float4(wi.x - a.x, wi.y - a.y, wi.z - a.z, wi.w - a.w);
    }
    __syncthreads();

    const float4 base = wsum[wid];
    // exclusive prefix for this thread's first bin
    const float4 ex = make_float4(base.x + incl.x - tot.x,
                                  base.y + incl.y - tot.y,
                                  base.z + incl.z - tot.z,
                                  base.w + incl.w - tot.w);

    float4* o = reinterpret_cast<float4*>(out) + (size_t)tid * PER_THR * F4 + j;
#pragma unroll
    for (int i = 0; i < PER_THR; ++i) {
        o[(size_t)i * F4] = make_float4(ex.x + v[i].x, ex.y + v[i].y,
                                        ex.z + v[i].z, ex.w + v[i].w);
    }
}

extern "C" void kernel_launch(void* const* d_in, const int* in_sizes, int n_in,
                              void* d_out, int out_size)
{
    const float* emb    = (const float*)d_in[0];
    const int*   starts = (const int*)d_in[1];
    const int*   ends   = (const int*)d_in[2];
    const int*   nnp    = (const int*)d_in[3];
    float*       out    = (float*)d_out;

    const int smem = MAX_TOKENS * sizeof(float4);   // 128 KB
    static bool attr_set = false;
    if (!attr_set) {
        cudaFuncSetAttribute(span_onepass_kernel,
                             cudaFuncAttributeMaxDynamicSharedMemorySize, smem);
        attr_set = true;
    }
    span_onepass_kernel<<<F4, NTHR, smem>>>(emb, starts, ends, nnp, out);
}

// round 15
// speedup vs baseline: 1.0136x; 1.0136x over previous
#include <cuda_runtime.h>
#include <cuda_bf16.h>

// SpanIndexEncoder: out[t] = sum over nodes n (n<num_nodes, s_n<=t<=e_n) of emb[n]
// ONE persistent kernel (592 co-resident blocks), R8's fast coalesced phases fused:
//   P0: classify boundary events into per-quarter (4-token) lists
//   P1: per-quarter sums: coalesced batched gathers of signed event rows
//   P2: block-per-feature exclusive scan over 2048 quarter sums
//   P3: apply: quarter prefix + 4-wide batched predicated event adds; store out.
// Grid barrier: monotonic counter (phase target = next multiple of GRID) -> valid
// across graph replays. g_qcnt self-resets in P3. Globals zero-init at module load.

#define MAX_TOKENS 8192
#define MAX_NODES  8192
#define FEAT       256
#define F4         (FEAT / 4)        // 64 float4 columns
#define NQ         (MAX_TOKENS / 4)  // 2048 quarters
#define CAP_Q      16384             // absolute worst case events in one quarter
#define GRID       592               // 148 SMs x 4 blocks, all co-resident
#define BLOCK      256

// event word: bits[0:13)=node, bits[13:15)=token-within-quarter, bit15=sign(1=minus)
__device__ unsigned g_qev[(size_t)NQ * CAP_Q];
__device__ int      g_qcnt[NQ];          // self-resetting
__device__ float    g_q[NQ * FEAT];      // quarter sums -> exclusive prefixes
__device__ unsigned g_count;             // monotonic barrier counter

__device__ __forceinline__ void gsync() {
    __threadfence();                     // make this thread's writes device-visible
    __syncthreads();
    if (threadIdx.x == 0) {
        unsigned v = atomicAdd(&g_count, 1u);
        unsigned target = (v / GRID + 1u) * GRID;
        while (*(volatile unsigned*)&g_count < target) { }
    }
    __syncthreads();
    __threadfence();
}

__device__ __forceinline__ float4 sgn_row(const float4* emb4, unsigned w, int j) {
    const float sg = (w & (1u << 15)) ? -1.f : 1.f;
    const float4 v = emb4[(size_t)(w & 8191u) * F4 + j];
    return make_float4(sg * v.x, sg * v.y, sg * v.z, sg * v.w);
}

__global__ void __launch_bounds__(BLOCK, 4) span_persistent_kernel(
    const float* __restrict__ emb,
    const int*   __restrict__ starts,
    const int*   __restrict__ ends,
    const int*   __restrict__ num_nodes_p,
    float*       __restrict__ out)
{
    __shared__ float4 sred[BLOCK];       // P1 reduction
    __shared__ float  swsum[8];          // P2 cross-warp scan

    const int bid = blockIdx.x;
    const int tid = threadIdx.x;
    const float4* emb4 = reinterpret_cast<const float4*>(emb);

    // ================= P0: classify =================
    {
        const int n = bid * BLOCK + tid;
        if (n < num_nodes_p[0]) {
            const int s = starts[n];
            const int e = ends[n];
            if (s <= e) {
                int q = s >> 2;
                int p = atomicAdd(&g_qcnt[q], 1);
                g_qev[(size_t)q * CAP_Q + p] = (unsigned)n | ((unsigned)(s & 3) << 13);
                const int e1 = e + 1;
                if (e1 < MAX_TOKENS) {
                    q = e1 >> 2;
                    p = atomicAdd(&g_qcnt[q], 1);
                    g_qev[(size_t)q * CAP_Q + p] =
                        (unsigned)n | ((unsigned)(e1 & 3) << 13) | (1u << 15);
                }
            }
        }
    }
    gsync();

    // ================= P1: per-quarter sums =================
    {
        const int j   = tid & 63;        // float4 column (warp lanes span j -> coalesced)
        const int grp = tid >> 6;        // 0..3 event groups
        for (int q = bid; q < NQ; q += GRID) {
            const int cnt = g_qcnt[q];
            const unsigned* evq = g_qev + (size_t)q * CAP_Q;
            float4 s = make_float4(0.f, 0.f, 0.f, 0.f);
            for (int i = grp; i < cnt; i += 4) {
                const float4 a = sgn_row(emb4, evq[i], j);
                s.x += a.x; s.y += a.y; s.z += a.z; s.w += a.w;
            }
            sred[tid] = s;
            __syncthreads();
            if (grp == 0) {
                const float4 a = sred[tid + 64], b = sred[tid + 128], c = sred[tid + 192];
                s.x += a.x + b.x + c.x;
                s.y += a.y + b.y + c.y;
                s.z += a.z + b.z + c.z;
                s.w += a.w + b.w + c.w;
                *reinterpret_cast<float4*>(&g_q[(size_t)q * FEAT + (j << 2)]) = s;
            }
            __syncthreads();
        }
    }
    gsync();

    // ================= P2: scan (blocks 0..255, one feature each) =================
    if (bid < FEAT) {
        const int f    = bid;
        const int lane = tid & 31;
        const int wid  = tid >> 5;

        float v[8];
#pragma unroll
        for (int k = 0; k < 8; ++k)
            v[k] = g_q[(size_t)(tid * 8 + k) * FEAT + f];
#pragma unroll
        for (int k = 1; k < 8; ++k) v[k] += v[k - 1];

        const float tot = v[7];
        float incl = tot;
#pragma unroll
        for (int d = 1; d < 32; d <<= 1) {
            const float t = __shfl_up_sync(0xffffffffu, incl, d);
            if (lane >= d) incl += t;
        }
        if (lane == 31) swsum[wid] = incl;
        __syncthreads();
        if (wid == 0 && lane < 8) {
            float a = swsum[lane];
            float wi = a;
#pragma unroll
            for (int d = 1; d < 8; d <<= 1) {
                const float t = __shfl_up_sync(0xffu, wi, d);
                if (lane >= d) wi += t;
            }
            swsum[lane] = wi - a;        // exclusive warp base
        }
        __syncthreads();

        const float ex = swsum[wid] + incl - tot;   // exclusive prefix of first owned quarter
        g_q[(size_t)(tid * 8 + 0) * FEAT + f] = ex;
#pragma unroll
        for (int k = 1; k < 8; ++k)
            g_q[(size_t)(tid * 8 + k) * FEAT + f] = ex + v[k - 1];
    }
    gsync();

    // ================= P3: apply + self-reset =================
    {
        const int j = tid & 63;
        const int t = tid >> 6;          // token-within-quarter
        for (int q = bid; q < NQ; q += GRID) {
            const int cnt = g_qcnt[q];
            const unsigned* evq = g_qev + (size_t)q * CAP_Q;

            float4 r = *reinterpret_cast<const float4*>(&g_q[(size_t)q * FEAT + (j << 2)]);

            int i = 0;
            for (; i + 4 <= cnt; i += 4) {   // 4-wide batch: all loads independent
                const unsigned w0 = evq[i], w1 = evq[i+1], w2 = evq[i+2], w3 = evq[i+3];
                const float4 v0 = sgn_row(emb4, w0, j);
                const float4 v1 = sgn_row(emb4, w1, j);
                const float4 v2 = sgn_row(emb4, w2, j);
                const float4 v3 = sgn_row(emb4, w3, j);
                const float p0 = (int)((w0 >> 13) & 3) <= t ? 1.f : 0.f;
                const float p1 = (int)((w1 >> 13) & 3) <= t ? 1.f : 0.f;
                const float p2 = (int)((w2 >> 13) & 3) <= t ? 1.f : 0.f;
                const float p3 = (int)((w3 >> 13) & 3) <= t ? 1.f : 0.f;
                r.x += p0*v0.x + p1*v1.x + p2*v2.x + p3*v3.x;
                r.y += p0*v0.y + p1*v1.y + p2*v2.y + p3*v3.y;
                r.z += p0*v0.z + p1*v1.z + p2*v2.z + p3*v3.z;
                r.w += p0*v0.w + p1*v1.w + p2*v2.w + p3*v3.w;
            }
            for (; i < cnt; ++i) {
                const unsigned w = evq[i];
                const float4 v = sgn_row(emb4, w, j);
                const float p = (int)((w >> 13) & 3) <= t ? 1.f : 0.f;
                r.x += p*v.x; r.y += p*v.y; r.z += p*v.z; r.w += p*v.w;
            }

            *reinterpret_cast<float4*>(out + (size_t)(q * 4 + t) * FEAT + (j << 2)) = r;

            __syncthreads();             // all threads consumed cnt
            if (tid == 0) g_qcnt[q] = 0; // reset for next graph replay
        }
    }
}

extern "C" void kernel_launch(void* const* d_in, const int* in_sizes, int n_in,
                              void* d_out, int out_size)
{
    const float* emb    = (const float*)d_in[0];
    const int*   starts = (const int*)d_in[1];
    const int*   ends   = (const int*)d_in[2];
    const int*   nnp    = (const int*)d_in[3];
    float*       out    = (float*)d_out;

    span_persistent_kernel<<<GRID, BLOCK>>>(emb, starts, ends, nnp, out);
}